// round 3
// baseline (speedup 1.0000x reference)
#include <cuda_runtime.h>
#include <cstdint>

// Problem constants
#define BB   8
#define CIN  128
#define HH   128
#define WW   128
#define HWP  (HH*WW)          // 16384
#define COUT 256
#define GG   8

// Scratch (static device globals — no allocation)
__device__ float d_P[BB * CIN * 52];        // pooled+nothing: [b][ch][52] (br0:0..10, br1:11..21, br2:22..36, br3:37..51)
__device__ float d_Q[BB * GG * 32 * 16];    // merged grids per (b,g): [32][16] (padded)
__device__ float d_GI[BB * GG * 96 * 16];   // Wih-folded grids + bih
__device__ float d_Wcomb[GG * 96 * 16];     // Whh @ W_center per group

// ---------------------------------------------------------------------------
// K1: adaptive average pooling of x -> d_P.
// Block = (b,ch) (1024 blocks, 128 threads). Single pass over the 128x128
// image accumulating column-wise h-bin sums for partitions {1,11,3,5}.
// Adaptive-pool bins can OVERLAP by one row (e_i may exceed s_{i+1}); each row
// is added to its main bin i1 = floor(h*O/128) and conditionally to i1-1/i1+1.
// ---------------------------------------------------------------------------
__device__ __forceinline__ void acc_bin(float* T, int O, int h, int w, float v) {
    int i1 = (h * O) >> 7;
    T[i1 * 128 + w] += v;
    if (i1 > 0) {
        int e0 = (i1 * 128 + O - 1) / O;          // e_{i1-1}
        if (h < e0) T[(i1 - 1) * 128 + w] += v;
    }
    if (i1 < O - 1) {
        int s1 = ((i1 + 1) * 128) / O;            // s_{i1+1}
        if (h >= s1) T[(i1 + 1) * 128 + w] += v;
    }
}

__global__ void k_pool(const float* __restrict__ x) {
    __shared__ float sm1[128];
    __shared__ float T11[11 * 128];
    __shared__ float T3[3 * 128];
    __shared__ float T5[5 * 128];

    int w = threadIdx.x;           // 0..127
    int bc = blockIdx.x;           // b*128+ch

    for (int i = w; i < 11 * 128; i += 128) T11[i] = 0.f;
    for (int i = w; i < 3 * 128;  i += 128) T3[i]  = 0.f;
    for (int i = w; i < 5 * 128;  i += 128) T5[i]  = 0.f;
    __syncthreads();

    const float* xp = x + (size_t)bc * HWP + w;
    float cs = 0.f;
#pragma unroll 4
    for (int h = 0; h < 128; ++h) {
        float v = xp[h * 128];
        cs += v;
        acc_bin(T11, 11, h, w, v);
        acc_bin(T3,   3, h, w, v);
        acc_bin(T5,   5, h, w, v);
    }
    sm1[w] = cs;
    __syncthreads();

    int t = threadIdx.x;
    if (t < 52) {
        float sum = 0.f;
        float cntH, cntW;
        if (t < 11) {                 // br0 (1,11): pool H fully, W into 11 bins
            int j = t;
            int s = (j * 128) / 11, e = ((j + 1) * 128 + 10) / 11;
            for (int ww = s; ww < e; ++ww) sum += sm1[ww];
            cntH = 128.f; cntW = (float)(e - s);
        } else if (t < 22) {          // br1 (11,1)
            int i = t - 11;
            int sH = (i * 128) / 11, eH = ((i + 1) * 128 + 10) / 11;
            for (int ww = 0; ww < 128; ++ww) sum += T11[i * 128 + ww];
            cntH = (float)(eH - sH); cntW = 128.f;
        } else if (t < 37) {          // br2 (3,5)
            int u = t - 22; int i = u / 5, j = u % 5;
            int sH = (i * 128) / 3, eH = ((i + 1) * 128 + 2) / 3;
            int s = (j * 128) / 5, e = ((j + 1) * 128 + 4) / 5;
            for (int ww = s; ww < e; ++ww) sum += T3[i * 128 + ww];
            cntH = (float)(eH - sH); cntW = (float)(e - s);
        } else {                      // br3 (5,3)
            int u = t - 37; int i = u / 3, j = u % 3;
            int sH = (i * 128) / 5, eH = ((i + 1) * 128 + 4) / 5;
            int s = (j * 128) / 3, e = ((j + 1) * 128 + 2) / 3;
            for (int ww = s; ww < e; ++ww) sum += T5[i * 128 + ww];
            cntH = (float)(eH - sH); cntW = (float)(e - s);
        }
        d_P[bc * 52 + t] = sum / (cntH * cntW);
    }
}

// ---------------------------------------------------------------------------
// K2: per-channel spatial linear (Wl,bl) + grouped merge conv folded into
// tiny grids: d_Q[b][g][ml][u], ml = GRU-input channel index within group.
// ---------------------------------------------------------------------------
__global__ void k_q(const float* __restrict__ Wm,
                    const float* __restrict__ W0, const float* __restrict__ b0,
                    const float* __restrict__ W1, const float* __restrict__ b1,
                    const float* __restrict__ W2, const float* __restrict__ b2,
                    const float* __restrict__ W3, const float* __restrict__ b3) {
    int bg = blockIdx.x;               // 0..63
    int b = bg >> 3, g = bg & 7;
    int br = g >> 1;
    const float* Wl; const float* bl; int cdim, base;
    if (br == 0)      { Wl = W0; bl = b0; cdim = 11; base = 0;  }
    else if (br == 1) { Wl = W1; bl = b1; cdim = 11; base = 11; }
    else if (br == 2) { Wl = W2; bl = b2; cdim = 15; base = 22; }
    else              { Wl = W3; bl = b3; cdim = 15; base = 37; }

    int t = threadIdx.x;               // 512 threads
    int ml = t >> 4, u = t & 15;
    float out = 0.f;
    if (u < cdim) {
        int gl = ml >> 1, o = ml & 1;
        int gm = 16 * g + gl;
#pragma unroll
        for (int j = 0; j < 4; ++j) {
            int ch = 64 * (g & 1) + 4 * gl + j;
            const float* Pp = &d_P[(b * 128 + ch) * 52 + base];
            float q = bl[u];
            for (int v = 0; v < cdim; ++v) q += Wl[u * cdim + v] * Pp[v];
            out += Wm[gm * 8 + o * 4 + j] * q;
        }
    }
    d_Q[(size_t)bg * 512 + t] = out;   // padded entries (u>=cdim) -> 0
}

// ---------------------------------------------------------------------------
// K3: fold GRU input projection: d_GI[b][g][o][u] = bih + Wih @ Q
// ---------------------------------------------------------------------------
__global__ void k_gi(const float* __restrict__ Wih, const float* __restrict__ bih) {
    int bg = blockIdx.x;               // 0..63
    int g = bg & 7;
    __shared__ float sQ[32 * 16];
    int t = threadIdx.x;               // 512
    sQ[t] = d_Q[(size_t)bg * 512 + t];
    __syncthreads();
    for (int idx = t; idx < 96 * 16; idx += 512) {
        int o = idx >> 4, u = idx & 15;
        float acc = bih[g * 96 + o];
        const float* Wr = &Wih[(size_t)(g * 96 + o) * 32];
#pragma unroll
        for (int ml = 0; ml < 32; ++ml) acc += Wr[ml] * sQ[ml * 16 + u];
        d_GI[(size_t)bg * 1536 + idx] = acc;
    }
}

// ---------------------------------------------------------------------------
// K4: Wcomb[g] = Whh[g] @ W_center[g]  (96x32 @ 32x16 -> 96x16)
// ---------------------------------------------------------------------------
__global__ void k_wcomb(const float* __restrict__ Whh, const float* __restrict__ Wc) {
    int g = blockIdx.x;
    int t = threadIdx.x;               // 512
    __shared__ float sWc[512];
    sWc[t] = Wc[g * 512 + t];
    __syncthreads();
    for (int idx = t; idx < 96 * 16; idx += 512) {
        int o = idx >> 4, i = idx & 15;
        float acc = 0.f;
        const float* Wr = &Whh[(size_t)(g * 96 + o) * 32];
#pragma unroll
        for (int h = 0; h < 32; ++h) acc += Wr[h] * sWc[h * 16 + i];
        d_Wcomb[(size_t)g * 1536 + idx] = acc;
    }
}

// ---------------------------------------------------------------------------
// K5: main fused kernel. One thread = one (pixel, GRU-group).
// gh via precomposed Wcomb @ x_g, gi via 4-tap interp of GI grids,
// cg via W_center row GEMV, GRU gates, write output.
// ---------------------------------------------------------------------------
__device__ __forceinline__ float dot16(const float4* __restrict__ r,
                                       const float* __restrict__ xv) {
    float4 a = r[0], b = r[1], c = r[2], d = r[3];
    float s0 = a.x * xv[0];  s0 += a.y * xv[1];  s0 += a.z * xv[2];  s0 += a.w * xv[3];
    float s1 = b.x * xv[4];  s1 += b.y * xv[5];  s1 += b.z * xv[6];  s1 += b.w * xv[7];
    float s2 = c.x * xv[8];  s2 += c.y * xv[9];  s2 += c.z * xv[10]; s2 += c.w * xv[11];
    float s3 = d.x * xv[12]; s3 += d.y * xv[13]; s3 += d.z * xv[14]; s3 += d.w * xv[15];
    return (s0 + s1) + (s2 + s3);
}

__device__ __forceinline__ float sigf(float a) {
    return __fdividef(1.f, 1.f + __expf(-a));
}

__global__ void __launch_bounds__(256, 4) k_main(const float* __restrict__ x,
                                                 const float* __restrict__ Wc,
                                                 const float* __restrict__ bhh,
                                                 float* __restrict__ out) {
    __shared__ __align__(16) float sWcomb[96 * 16];
    __shared__ __align__(16) float sGI[96 * 16];
    __shared__ __align__(16) float sWc[32 * 16];
    __shared__ float sbhh[96];

    int tid = threadIdx.x;
    int tile = blockIdx.x & 63;
    int g    = (blockIdx.x >> 6) & 7;
    int b    = blockIdx.x >> 9;

    for (int i = tid; i < 96 * 16; i += 256) {
        sWcomb[i] = d_Wcomb[(size_t)g * 1536 + i];
        sGI[i]    = d_GI[((size_t)(b * 8 + g)) * 1536 + i];
    }
    for (int i = tid; i < 512; i += 256) sWc[i] = Wc[g * 512 + i];
    if (tid < 96) sbhh[tid] = bhh[g * 96 + tid];
    __syncthreads();

    int p = tile * 256 + tid;
    int h = p >> 7, w = p & 127;

    float xv[16];
    const float* xb = x + ((size_t)(b * 128 + g * 16)) * HWP + p;
#pragma unroll
    for (int i = 0; i < 16; ++i) xv[i] = xb[(size_t)i * HWP];

    // interpolation setup (branch is uniform per block)
    int br = g >> 1;
    int nH = (br == 0) ? 1 : (br == 1) ? 11 : (br == 2) ? 3 : 5;
    int nW = (br == 0) ? 11 : (br == 1) ? 1 : (br == 2) ? 5 : 3;
    int ci = (br == 1) ? 1 : (br == 2) ? 5 : (br == 3) ? 3 : 0;

    float fh = 0.f; int i0 = 0;
    if (nH > 1) {
        float s = (float)(h * (nH - 1)) * (1.f / 127.f);
        i0 = (int)s; if (i0 > nH - 2) i0 = nH - 2;
        fh = s - (float)i0;
    }
    float fw = 0.f; int j0 = 0;
    if (nW > 1) {
        float s = (float)(w * (nW - 1)) * (1.f / 127.f);
        j0 = (int)s; if (j0 > nW - 2) j0 = nW - 2;
        fw = s - (float)j0;
    }
    int p00 = i0 * ci + j0;
    float w00 = (1.f - fh) * (1.f - fw);
    float w01 = (1.f - fh) * fw;
    float w10 = fh * (1.f - fw);
    float w11 = fh * fw;

    float* ob = out + ((size_t)(b * 256 + g)) * HWP + p;
    const float4* Wc4 = (const float4*)sWc;
    const float4* Wb4 = (const float4*)sWcomb;

#pragma unroll 2
    for (int o = 0; o < 32; ++o) {
        float cg = dot16(Wc4 + o * 4, xv);
        float hr = sbhh[o]      + dot16(Wb4 + o * 4, xv);
        float hz = sbhh[o + 32] + dot16(Wb4 + (o + 32) * 4, xv);
        float hn = sbhh[o + 64] + dot16(Wb4 + (o + 64) * 4, xv);

        const float* g0 = sGI + o * 16 + p00;
        const float* g1 = sGI + (o + 32) * 16 + p00;
        const float* g2 = sGI + (o + 64) * 16 + p00;
        float ir  = w00 * g0[0] + w01 * g0[1] + w10 * g0[ci] + w11 * g0[ci + 1];
        float iz  = w00 * g1[0] + w01 * g1[1] + w10 * g1[ci] + w11 * g1[ci + 1];
        float inn = w00 * g2[0] + w01 * g2[1] + w10 * g2[ci] + w11 * g2[ci + 1];

        float r = sigf(ir + hr);
        float z = sigf(iz + hz);
        float e = __expf(-2.f * (inn + r * hn));
        float nt = __fdividef(2.f, 1.f + e) - 1.f;       // tanh
        float y = nt + z * (cg - nt);

        ob[(size_t)(o * 8) * HWP] = y;
    }
}

// ---------------------------------------------------------------------------
extern "C" void kernel_launch(void* const* d_in, const int* in_sizes, int n_in,
                              void* d_out, int out_size) {
    (void)in_sizes; (void)n_in; (void)out_size;
    const float* x   = (const float*)d_in[0];
    const float* Wc  = (const float*)d_in[1];
    const float* W0  = (const float*)d_in[2];
    const float* b0  = (const float*)d_in[3];
    const float* W1  = (const float*)d_in[4];
    const float* b1  = (const float*)d_in[5];
    const float* W2  = (const float*)d_in[6];
    const float* b2  = (const float*)d_in[7];
    const float* W3  = (const float*)d_in[8];
    const float* b3  = (const float*)d_in[9];
    const float* Wm  = (const float*)d_in[10];
    const float* Wih = (const float*)d_in[11];
    const float* Whh = (const float*)d_in[12];
    const float* bih = (const float*)d_in[13];
    const float* bhh = (const float*)d_in[14];
    float* out = (float*)d_out;

    k_pool<<<BB * CIN, 128>>>(x);
    k_q<<<BB * GG, 512>>>(Wm, W0, b0, W1, b1, W2, b2, W3, b3);
    k_gi<<<BB * GG, 512>>>(Wih, bih);
    k_wcomb<<<GG, 512>>>(Whh, Wc);
    k_main<<<BB * GG * (HWP / 256), 256>>>(x, Wc, bhh, out);
}

// round 4
// speedup vs baseline: 1.1389x; 1.1389x over previous
#include <cuda_runtime.h>
#include <cstdint>

// Problem constants
#define BB   8
#define CIN  128
#define HH   128
#define WW   128
#define HWP  (HH*WW)          // 16384
#define COUT 256
#define GG   8

// Scratch (static device globals — no allocation)
__device__ float  d_P[BB * CIN * 52];          // pooled grids: [b][ch][52]
__device__ float2 d_GIp[BB * GG * 32 * 16];    // (gi_r, gi_z) packed grids
__device__ float  d_GIn[BB * GG * 32 * 16];    // gi_n grids
__device__ float2 d_WpackA[GG * 32 * 16];      // (Wcomb_r, Wcomb_z) per group
__device__ float2 d_WpackB[GG * 32 * 16];      // (Wcomb_n, W_center) per group

// ---- packed f32x2 helpers (FFMA2 — only reachable via PTX) ----------------
__device__ __forceinline__ unsigned long long pk2(float lo, float hi) {
    unsigned long long r;
    asm("mov.b64 %0, {%1,%2};" : "=l"(r) : "f"(lo), "f"(hi));
    return r;
}
__device__ __forceinline__ void upk2(float& lo, float& hi, unsigned long long v) {
    asm("mov.b64 {%0,%1}, %2;" : "=f"(lo), "=f"(hi) : "l"(v));
}
__device__ __forceinline__ unsigned long long fma2(unsigned long long a,
                                                   unsigned long long b,
                                                   unsigned long long c) {
    unsigned long long d;
    asm("fma.rn.f32x2 %0, %1, %2, %3;" : "=l"(d) : "l"(a), "l"(b), "l"(c));
    return d;
}
__device__ __forceinline__ unsigned long long mul2(unsigned long long a,
                                                   unsigned long long b) {
    unsigned long long d;
    asm("mul.rn.f32x2 %0, %1, %2;" : "=l"(d) : "l"(a), "l"(b));
    return d;
}

// ---------------------------------------------------------------------------
// K1: adaptive average pooling of x -> d_P. Block = (b,ch). Bins may overlap
// by one row (floor/ceil bins), handled by conditional side-bin adds.
// ---------------------------------------------------------------------------
__device__ __forceinline__ void acc_bin(float* T, int O, int h, int w, float v) {
    int i1 = (h * O) >> 7;
    T[i1 * 128 + w] += v;
    if (i1 > 0) {
        int e0 = (i1 * 128 + O - 1) / O;
        if (h < e0) T[(i1 - 1) * 128 + w] += v;
    }
    if (i1 < O - 1) {
        int s1 = ((i1 + 1) * 128) / O;
        if (h >= s1) T[(i1 + 1) * 128 + w] += v;
    }
}

__global__ void k_pool(const float* __restrict__ x) {
    __shared__ float sm1[128];
    __shared__ float T11[11 * 128];
    __shared__ float T3[3 * 128];
    __shared__ float T5[5 * 128];

    int w = threadIdx.x;
    int bc = blockIdx.x;

    for (int i = w; i < 11 * 128; i += 128) T11[i] = 0.f;
    for (int i = w; i < 3 * 128;  i += 128) T3[i]  = 0.f;
    for (int i = w; i < 5 * 128;  i += 128) T5[i]  = 0.f;
    __syncthreads();

    const float* xp = x + (size_t)bc * HWP + w;
    float cs = 0.f;
#pragma unroll 4
    for (int h = 0; h < 128; ++h) {
        float v = xp[h * 128];
        cs += v;
        acc_bin(T11, 11, h, w, v);
        acc_bin(T3,   3, h, w, v);
        acc_bin(T5,   5, h, w, v);
    }
    sm1[w] = cs;
    __syncthreads();

    int t = threadIdx.x;
    if (t < 52) {
        float sum = 0.f;
        float cntH, cntW;
        if (t < 11) {                 // br0 (1,11)
            int j = t;
            int s = (j * 128) / 11, e = ((j + 1) * 128 + 10) / 11;
            for (int ww = s; ww < e; ++ww) sum += sm1[ww];
            cntH = 128.f; cntW = (float)(e - s);
        } else if (t < 22) {          // br1 (11,1)
            int i = t - 11;
            int sH = (i * 128) / 11, eH = ((i + 1) * 128 + 10) / 11;
            for (int ww = 0; ww < 128; ++ww) sum += T11[i * 128 + ww];
            cntH = (float)(eH - sH); cntW = 128.f;
        } else if (t < 37) {          // br2 (3,5)
            int u = t - 22; int i = u / 5, j = u % 5;
            int sH = (i * 128) / 3, eH = ((i + 1) * 128 + 2) / 3;
            int s = (j * 128) / 5, e = ((j + 1) * 128 + 4) / 5;
            for (int ww = s; ww < e; ++ww) sum += T3[i * 128 + ww];
            cntH = (float)(eH - sH); cntW = (float)(e - s);
        } else {                      // br3 (5,3)
            int u = t - 37; int i = u / 3, j = u % 3;
            int sH = (i * 128) / 5, eH = ((i + 1) * 128 + 4) / 5;
            int s = (j * 128) / 3, e = ((j + 1) * 128 + 2) / 3;
            for (int ww = s; ww < e; ++ww) sum += T5[i * 128 + ww];
            cntH = (float)(eH - sH); cntW = (float)(e - s);
        }
        d_P[bc * 52 + t] = sum / (cntH * cntW);
    }
}

// ---------------------------------------------------------------------------
// K2 (fused k_q + k_gi): per-channel spatial linear + grouped merge conv into
// smem grids Q, then GRU input projection folded over Q -> packed GI grids.
// ---------------------------------------------------------------------------
__global__ void k_qgi(const float* __restrict__ Wm,
                      const float* __restrict__ W0, const float* __restrict__ b0,
                      const float* __restrict__ W1, const float* __restrict__ b1,
                      const float* __restrict__ W2, const float* __restrict__ b2,
                      const float* __restrict__ W3, const float* __restrict__ b3,
                      const float* __restrict__ Wih, const float* __restrict__ bih) {
    __shared__ float sQ[32 * 16];

    int bg = blockIdx.x;               // 0..63
    int b = bg >> 3, g = bg & 7;
    int br = g >> 1;
    const float* Wl; const float* bl; int cdim, base;
    if (br == 0)      { Wl = W0; bl = b0; cdim = 11; base = 0;  }
    else if (br == 1) { Wl = W1; bl = b1; cdim = 11; base = 11; }
    else if (br == 2) { Wl = W2; bl = b2; cdim = 15; base = 22; }
    else              { Wl = W3; bl = b3; cdim = 15; base = 37; }

    int t = threadIdx.x;               // 512 threads
    int ml = t >> 4, u = t & 15;
    float out = 0.f;
    if (u < cdim) {
        int gl = ml >> 1, o = ml & 1;
        int gm = 16 * g + gl;
#pragma unroll
        for (int j = 0; j < 4; ++j) {
            int ch = 64 * (g & 1) + 4 * gl + j;
            const float* Pp = &d_P[(b * 128 + ch) * 52 + base];
            float q = bl[u];
            for (int v = 0; v < cdim; ++v) q += Wl[u * cdim + v] * Pp[v];
            out += Wm[gm * 8 + o * 4 + j] * q;
        }
    }
    sQ[t] = out;
    __syncthreads();

    // GI: rows o (r), o+32 (z), o+64 (n), each a 32-dot over sQ column u
    int o = t >> 4;                    // 0..31
    float ar = bih[g * 96 + o];
    float az = bih[g * 96 + 32 + o];
    float an = bih[g * 96 + 64 + o];
    const float* Wr = &Wih[(size_t)(g * 96 + o) * 32];
    const float* Wz = Wr + 32 * 32;
    const float* Wn = Wz + 32 * 32;
#pragma unroll
    for (int ml2 = 0; ml2 < 32; ++ml2) {
        float q = sQ[ml2 * 16 + u];
        ar += Wr[ml2] * q;
        az += Wz[ml2] * q;
        an += Wn[ml2] * q;
    }
    d_GIp[(size_t)bg * 512 + t] = make_float2(ar, az);
    d_GIn[(size_t)bg * 512 + t] = an;
}

// ---------------------------------------------------------------------------
// K3: Wcomb = Whh @ W_center per group, stored as interleaved gate pairs:
//   WpackA[o][i] = (Wcomb_r[o][i], Wcomb_z[o][i])
//   WpackB[o][i] = (Wcomb_n[o][i], W_center[o][i])
// ---------------------------------------------------------------------------
__global__ void k_wcomb(const float* __restrict__ Whh, const float* __restrict__ Wc) {
    int g = blockIdx.x;
    int t = threadIdx.x;               // 512
    __shared__ float sWc[512];
    sWc[t] = Wc[g * 512 + t];
    __syncthreads();

    int o = t >> 4, i = t & 15;
    const float* Wr = &Whh[(size_t)(g * 96 + o) * 32];
    const float* Wz = Wr + 32 * 32;
    const float* Wn = Wz + 32 * 32;
    float ar = 0.f, az = 0.f, an = 0.f;
#pragma unroll
    for (int h = 0; h < 32; ++h) {
        float c = sWc[h * 16 + i];
        ar += Wr[h] * c;
        az += Wz[h] * c;
        an += Wn[h] * c;
    }
    d_WpackA[(size_t)g * 512 + t] = make_float2(ar, az);
    d_WpackB[(size_t)g * 512 + t] = make_float2(an, sWc[t]);
}

// ---------------------------------------------------------------------------
// K4: main fused kernel, packed-f32x2 version. One thread = one (pixel,group).
// Per output channel o:
//   (hr,hz) = biasA + WpackA[o] . x   (16 FFMA2)
//   (hn,cg) = biasB + WpackB[o] . x   (16 FFMA2)
//   (ir,iz) = 4-tap interp of packed GI grid (4 FFMA2)
//   in      = 4-tap interp of scalar GIn grid
//   GRU gates -> y
// ---------------------------------------------------------------------------
__device__ __forceinline__ float sigf(float a) {
    return __fdividef(1.f, 1.f + __expf(-a));
}

__global__ void __launch_bounds__(256, 3) k_main(const float* __restrict__ x,
                                                 const float* __restrict__ bhh,
                                                 float* __restrict__ out) {
    __shared__ __align__(16) unsigned long long sWA[512];
    __shared__ __align__(16) unsigned long long sWB[512];
    __shared__ __align__(16) unsigned long long sGIp[512];
    __shared__ float sGIn[512];
    __shared__ unsigned long long sbA[32];
    __shared__ unsigned long long sbB[32];

    int tid = threadIdx.x;
    int tile = blockIdx.x & 63;
    int g    = (blockIdx.x >> 6) & 7;
    int b    = blockIdx.x >> 9;

    {
        const unsigned long long* wa = (const unsigned long long*)(d_WpackA + (size_t)g * 512);
        const unsigned long long* wb = (const unsigned long long*)(d_WpackB + (size_t)g * 512);
        const unsigned long long* gp = (const unsigned long long*)(d_GIp + (size_t)(b * 8 + g) * 512);
        const float* gn = d_GIn + (size_t)(b * 8 + g) * 512;
        for (int i = tid; i < 512; i += 256) {
            sWA[i]  = wa[i];
            sWB[i]  = wb[i];
            sGIp[i] = gp[i];
            sGIn[i] = gn[i];
        }
        if (tid < 32) {
            float br_ = bhh[g * 96 + tid];
            float bz_ = bhh[g * 96 + 32 + tid];
            float bn_ = bhh[g * 96 + 64 + tid];
            sbA[tid] = pk2(br_, bz_);
            sbB[tid] = pk2(bn_, 0.f);
        }
    }
    __syncthreads();

    int p = tile * 256 + tid;
    int h = p >> 7, w = p & 127;

    // load x for this pixel, duplicated into packed lanes
    unsigned long long xvd[16];
    const float* xb = x + ((size_t)(b * 128 + g * 16)) * HWP + p;
#pragma unroll
    for (int i = 0; i < 16; ++i) {
        float v = xb[(size_t)i * HWP];
        xvd[i] = pk2(v, v);
    }

    // interpolation setup (branch uniform per block)
    int br = g >> 1;
    int nH = (br == 0) ? 1 : (br == 1) ? 11 : (br == 2) ? 3 : 5;
    int nW = (br == 0) ? 11 : (br == 1) ? 1 : (br == 2) ? 5 : 3;
    int ci = (br == 1) ? 1 : (br == 2) ? 5 : (br == 3) ? 3 : 0;

    float fh = 0.f; int i0 = 0;
    if (nH > 1) {
        float s = (float)(h * (nH - 1)) * (1.f / 127.f);
        i0 = (int)s; if (i0 > nH - 2) i0 = nH - 2;
        fh = s - (float)i0;
    }
    float fw = 0.f; int j0 = 0;
    if (nW > 1) {
        float s = (float)(w * (nW - 1)) * (1.f / 127.f);
        j0 = (int)s; if (j0 > nW - 2) j0 = nW - 2;
        fw = s - (float)j0;
    }
    int p00 = i0 * ci + j0;
    float w00 = (1.f - fh) * (1.f - fw);
    float w01 = (1.f - fh) * fw;
    float w10 = fh * (1.f - fw);
    float w11 = fh * fw;
    unsigned long long w00d = pk2(w00, w00);
    unsigned long long w01d = pk2(w01, w01);
    unsigned long long w10d = pk2(w10, w10);
    unsigned long long w11d = pk2(w11, w11);

    float* ob = out + ((size_t)(b * 256 + g)) * HWP + p;

#pragma unroll 2
    for (int o = 0; o < 32; ++o) {
        unsigned long long accA = sbA[o];
        unsigned long long accB = sbB[o];
        const ulonglong2* A2 = (const ulonglong2*)(sWA + o * 16);
        const ulonglong2* B2 = (const ulonglong2*)(sWB + o * 16);
#pragma unroll
        for (int k = 0; k < 8; ++k) {
            ulonglong2 wa = A2[k];
            ulonglong2 wb = B2[k];
            accA = fma2(wa.x, xvd[2 * k],     accA);
            accA = fma2(wa.y, xvd[2 * k + 1], accA);
            accB = fma2(wb.x, xvd[2 * k],     accB);
            accB = fma2(wb.y, xvd[2 * k + 1], accB);
        }
        float hr, hz, hn, cg;
        upk2(hr, hz, accA);
        upk2(hn, cg, accB);

        const unsigned long long* gp = sGIp + o * 16 + p00;
        unsigned long long irz = mul2(w00d, gp[0]);
        irz = fma2(w01d, gp[1],      irz);
        irz = fma2(w10d, gp[ci],     irz);
        irz = fma2(w11d, gp[ci + 1], irz);
        float ir, iz;
        upk2(ir, iz, irz);

        const float* gn = sGIn + o * 16 + p00;
        float inn = w00 * gn[0] + w01 * gn[1] + w10 * gn[ci] + w11 * gn[ci + 1];

        float r = sigf(ir + hr);
        float z = sigf(iz + hz);
        float e = __expf(-2.f * (inn + r * hn));
        float nt = __fdividef(2.f, 1.f + e) - 1.f;       // tanh
        float y = nt + z * (cg - nt);

        ob[(size_t)(o * 8) * HWP] = y;
    }
}

// ---------------------------------------------------------------------------
extern "C" void kernel_launch(void* const* d_in, const int* in_sizes, int n_in,
                              void* d_out, int out_size) {
    (void)in_sizes; (void)n_in; (void)out_size;
    const float* x   = (const float*)d_in[0];
    const float* Wc  = (const float*)d_in[1];
    const float* W0  = (const float*)d_in[2];
    const float* b0  = (const float*)d_in[3];
    const float* W1  = (const float*)d_in[4];
    const float* b1  = (const float*)d_in[5];
    const float* W2  = (const float*)d_in[6];
    const float* b2  = (const float*)d_in[7];
    const float* W3  = (const float*)d_in[8];
    const float* b3  = (const float*)d_in[9];
    const float* Wm  = (const float*)d_in[10];
    const float* Wih = (const float*)d_in[11];
    const float* Whh = (const float*)d_in[12];
    const float* bih = (const float*)d_in[13];
    const float* bhh = (const float*)d_in[14];
    float* out = (float*)d_out;

    k_pool<<<BB * CIN, 128>>>(x);
    k_qgi<<<BB * GG, 512>>>(Wm, W0, b0, W1, b1, W2, b2, W3, b3, Wih, bih);
    k_wcomb<<<GG, 512>>>(Whh, Wc);
    k_main<<<BB * GG * (HWP / 256), 256>>>(x, bhh, out);
}

// round 5
// speedup vs baseline: 1.9556x; 1.7170x over previous
#include <cuda_runtime.h>
#include <cstdint>

// Problem constants
#define BB   8
#define CIN  128
#define HH   128
#define WW   128
#define HWP  (HH*WW)          // 16384
#define COUT 256
#define GG   8

// Scratch (static device globals — no allocation)
__device__ float  d_P[BB * CIN * 52];          // pooled grids: [b][ch][52]
__device__ float2 d_GIp[BB * GG * 32 * 16];    // (gi_r, gi_z) packed grids
__device__ float  d_GIn[BB * GG * 32 * 16];    // gi_n grids
__device__ float2 d_WpackA[GG * 32 * 16];      // (Wcomb_r, Wcomb_z) per group
__device__ float2 d_WpackB[GG * 32 * 16];      // (Wcomb_n, W_center) per group

// ---- packed f32x2 helpers (FFMA2 — only reachable via PTX) ----------------
__device__ __forceinline__ unsigned long long pk2(float lo, float hi) {
    unsigned long long r;
    asm("mov.b64 %0, {%1,%2};" : "=l"(r) : "f"(lo), "f"(hi));
    return r;
}
__device__ __forceinline__ void upk2(float& lo, float& hi, unsigned long long v) {
    asm("mov.b64 {%0,%1}, %2;" : "=f"(lo), "=f"(hi) : "l"(v));
}
__device__ __forceinline__ unsigned long long fma2(unsigned long long a,
                                                   unsigned long long b,
                                                   unsigned long long c) {
    unsigned long long d;
    asm("fma.rn.f32x2 %0, %1, %2, %3;" : "=l"(d) : "l"(a), "l"(b), "l"(c));
    return d;
}
__device__ __forceinline__ unsigned long long mul2(unsigned long long a,
                                                   unsigned long long b) {
    unsigned long long d;
    asm("mul.rn.f32x2 %0, %1, %2;" : "=l"(d) : "l"(a), "l"(b));
    return d;
}

// ---------------------------------------------------------------------------
// K1: adaptive average pooling via column cumsum checkpoints.
// All bins for target sizes {1,11,3,5} (floor-start / ceil-end, may overlap
// by one row) are differences of column cumulative sums at 33 fixed indices.
// Phase 1: each thread (one w-column) accumulates cs in a register, storing
// it to smem only at checkpoint rows. Phase 2: per-column h-bin sums. Phase 3:
// w-direction bin sums -> d_P.
// ---------------------------------------------------------------------------
// SLOT[k] = checkpoint slot index for cumsum after k rows, -1 if unused.
__device__ constexpr signed char SLOT[129] = {
    -1,-1,-1,-1,-1,-1,-1,-1,-1,-1,-1,   // 0..10
     0, 1,                              // 11,12
    -1,-1,-1,-1,-1,-1,-1,-1,-1,-1,      // 13..22
     2, 3, 4, 5,                        // 23,24,25,26
    -1,-1,-1,-1,-1,-1,-1,               // 27..33
     6, 7,                              // 34,35
    -1,-1,-1,-1,-1,-1,                  // 36..41
     8, 9,                              // 42,43
    -1,-1,                              // 44,45
    10,11,                              // 46,47
    -1,-1,-1,                           // 48..50
    12,13,                              // 51,52
    -1,-1,-1,-1,-1,                     // 53..57
    14,15,                              // 58,59
    -1,-1,-1,-1,-1,-1,-1,-1,-1,         // 60..68
    16,17,                              // 69,70
    -1,-1,-1,-1,-1,                     // 71..75
    18,19,                              // 76,77
    -1,-1,-1,                           // 78..80
    20,21,                              // 81,82
    -1,-1,                              // 83,84
    22,23,                              // 85,86
    -1,-1,-1,-1,-1,-1,                  // 87..92
    24,25,                              // 93,94
    -1,-1,-1,-1,-1,-1,-1,               // 95..101
    26,27,28,29,                        // 102,103,104,105
    -1,-1,-1,-1,-1,-1,-1,-1,-1,-1,      // 106..115
    30,31,                              // 116,117
    -1,-1,-1,-1,-1,-1,-1,-1,-1,-1,      // 118..127
    32                                  // 128
};

// 20 h-bins: [0]=full(O=1), [1..11]=O11, [12..14]=O3, [15..19]=O5
__device__ constexpr signed char HB_SSLOT[20] =
    {-1,  -1, 0, 2, 6,10,14,16,20,24,28,30,  -1, 8,22,  -1, 4,12,18,26};
__device__ constexpr signed char HB_ESLOT[20] =
    {32,   1, 3, 7,11,15,17,21,25,29,31,32,   9,23,32,   5,13,19,27,32};

__global__ void k_pool(const float* __restrict__ x) {
    __shared__ float CS[33 * 128];
    __shared__ float Hs[20 * 128];

    int w = threadIdx.x;           // 0..127
    int bc = blockIdx.x;           // b*128+ch

    const float* xp = x + (size_t)bc * HWP + w;
    float cs = 0.f;
#pragma unroll
    for (int h = 0; h < 128; ++h) {
        cs += xp[h * 128];
        int sl = SLOT[h + 1];
        if (sl >= 0) CS[sl * 128 + w] = cs;
    }
    __syncthreads();

    // per-column h-bin sums
#pragma unroll
    for (int bi = 0; bi < 20; ++bi) {
        float v = CS[(int)HB_ESLOT[bi] * 128 + w];
        if (HB_SSLOT[bi] >= 0) v -= CS[(int)HB_SSLOT[bi] * 128 + w];
        Hs[bi * 128 + w] = v;
    }
    __syncthreads();

    int t = threadIdx.x;
    if (t < 52) {
        float sum = 0.f;
        float cnt;
        if (t < 11) {                 // br0 (1,11): full H, w-bins O=11
            int j = t;
            int s = (j * 128) / 11, e = ((j + 1) * 128 + 10) / 11;
            for (int ww = s; ww < e; ++ww) sum += Hs[ww];
            cnt = 128.f * (float)(e - s);
        } else if (t < 22) {          // br1 (11,1)
            int i = t - 11;
            int sH = (i * 128) / 11, eH = ((i + 1) * 128 + 10) / 11;
            const float* Hp = &Hs[(1 + i) * 128];
            for (int ww = 0; ww < 128; ++ww) sum += Hp[ww];
            cnt = (float)(eH - sH) * 128.f;
        } else if (t < 37) {          // br2 (3,5)
            int u = t - 22; int i = u / 5, j = u % 5;
            int sH = (i * 128) / 3, eH = ((i + 1) * 128 + 2) / 3;
            int s = (j * 128) / 5, e = ((j + 1) * 128 + 4) / 5;
            const float* Hp = &Hs[(12 + i) * 128];
            for (int ww = s; ww < e; ++ww) sum += Hp[ww];
            cnt = (float)(eH - sH) * (float)(e - s);
        } else {                      // br3 (5,3)
            int u = t - 37; int i = u / 3, j = u % 3;
            int sH = (i * 128) / 5, eH = ((i + 1) * 128 + 4) / 5;
            int s = (j * 128) / 3, e = ((j + 1) * 128 + 2) / 3;
            const float* Hp = &Hs[(15 + i) * 128];
            for (int ww = s; ww < e; ++ww) sum += Hp[ww];
            cnt = (float)(eH - sH) * (float)(e - s);
        }
        d_P[bc * 52 + t] = sum / cnt;
    }
}

// ---------------------------------------------------------------------------
// K2 (fused k_q + k_gi + k_wcomb):
//   blocks 0..63  : per-channel spatial linear + merge conv -> Q (smem),
//                   then GRU input projection -> packed GI grids.
//   blocks 64..71 : Wcomb = Whh @ W_center, stored as interleaved gate pairs.
// ---------------------------------------------------------------------------
__global__ void k_qgi(const float* __restrict__ Wm,
                      const float* __restrict__ W0, const float* __restrict__ b0,
                      const float* __restrict__ W1, const float* __restrict__ b1,
                      const float* __restrict__ W2, const float* __restrict__ b2,
                      const float* __restrict__ W3, const float* __restrict__ b3,
                      const float* __restrict__ Wih, const float* __restrict__ bih,
                      const float* __restrict__ Whh, const float* __restrict__ Wc) {
    __shared__ float ssh[32 * 16];
    int t = threadIdx.x;               // 512 threads

    if (blockIdx.x >= 64) {
        // ---- wcomb part ----
        int g = blockIdx.x - 64;
        ssh[t] = Wc[g * 512 + t];
        __syncthreads();

        int o = t >> 4, i = t & 15;
        const float* Wr = &Whh[(size_t)(g * 96 + o) * 32];
        const float* Wz = Wr + 32 * 32;
        const float* Wn = Wz + 32 * 32;
        float ar = 0.f, az = 0.f, an = 0.f;
#pragma unroll
        for (int h = 0; h < 32; ++h) {
            float c = ssh[h * 16 + i];
            ar += Wr[h] * c;
            az += Wz[h] * c;
            an += Wn[h] * c;
        }
        d_WpackA[(size_t)g * 512 + t] = make_float2(ar, az);
        d_WpackB[(size_t)g * 512 + t] = make_float2(an, ssh[t]);
        return;
    }

    // ---- qgi part ----
    int bg = blockIdx.x;               // 0..63
    int b = bg >> 3, g = bg & 7;
    int br = g >> 1;
    const float* Wl; const float* bl; int cdim, base;
    if (br == 0)      { Wl = W0; bl = b0; cdim = 11; base = 0;  }
    else if (br == 1) { Wl = W1; bl = b1; cdim = 11; base = 11; }
    else if (br == 2) { Wl = W2; bl = b2; cdim = 15; base = 22; }
    else              { Wl = W3; bl = b3; cdim = 15; base = 37; }

    int ml = t >> 4, u = t & 15;
    float outq = 0.f;
    if (u < cdim) {
        int gl = ml >> 1, o = ml & 1;
        int gm = 16 * g + gl;
#pragma unroll
        for (int j = 0; j < 4; ++j) {
            int ch = 64 * (g & 1) + 4 * gl + j;
            const float* Pp = &d_P[(b * 128 + ch) * 52 + base];
            float q = bl[u];
            for (int v = 0; v < cdim; ++v) q += Wl[u * cdim + v] * Pp[v];
            outq += Wm[gm * 8 + o * 4 + j] * q;
        }
    }
    ssh[t] = outq;
    __syncthreads();

    int o = t >> 4;                    // 0..31
    float ar = bih[g * 96 + o];
    float az = bih[g * 96 + 32 + o];
    float an = bih[g * 96 + 64 + o];
    const float* Wr = &Wih[(size_t)(g * 96 + o) * 32];
    const float* Wz = Wr + 32 * 32;
    const float* Wn = Wz + 32 * 32;
#pragma unroll
    for (int ml2 = 0; ml2 < 32; ++ml2) {
        float q = ssh[ml2 * 16 + u];
        ar += Wr[ml2] * q;
        az += Wz[ml2] * q;
        an += Wn[ml2] * q;
    }
    d_GIp[(size_t)bg * 512 + t] = make_float2(ar, az);
    d_GIn[(size_t)bg * 512 + t] = an;
}

// ---------------------------------------------------------------------------
// K3: main fused kernel — packed f32x2 gates, 2 pixels per thread.
// Pixels p and p+256 share the same w column (fw/j0 identical), weight LDS
// is amortized over 64 FFMA2 per o instead of 32.
// ---------------------------------------------------------------------------
__device__ __forceinline__ float sigf(float a) {
    return __fdividef(1.f, 1.f + __expf(-a));
}
__device__ __forceinline__ float tanhfast(float a) {
    float e = __expf(-2.f * a);
    return __fdividef(2.f, 1.f + e) - 1.f;
}

__global__ void __launch_bounds__(256, 2) k_main(const float* __restrict__ x,
                                                 const float* __restrict__ bhh,
                                                 float* __restrict__ out) {
    __shared__ __align__(16) unsigned long long sWA[512];
    __shared__ __align__(16) unsigned long long sWB[512];
    __shared__ __align__(16) unsigned long long sGIp[512];
    __shared__ float sGIn[512];
    __shared__ unsigned long long sbA[32];
    __shared__ unsigned long long sbB[32];

    int tid = threadIdx.x;
    int tile = blockIdx.x & 31;          // 32 tiles of 512 pixels
    int g    = (blockIdx.x >> 5) & 7;
    int b    = blockIdx.x >> 8;

    {
        const unsigned long long* wa = (const unsigned long long*)(d_WpackA + (size_t)g * 512);
        const unsigned long long* wb = (const unsigned long long*)(d_WpackB + (size_t)g * 512);
        const unsigned long long* gp = (const unsigned long long*)(d_GIp + (size_t)(b * 8 + g) * 512);
        const float* gn = d_GIn + (size_t)(b * 8 + g) * 512;
        for (int i = tid; i < 512; i += 256) {
            sWA[i]  = wa[i];
            sWB[i]  = wb[i];
            sGIp[i] = gp[i];
            sGIn[i] = gn[i];
        }
        if (tid < 32) {
            float br_ = bhh[g * 96 + tid];
            float bz_ = bhh[g * 96 + 32 + tid];
            float bn_ = bhh[g * 96 + 64 + tid];
            sbA[tid] = pk2(br_, bz_);
            sbB[tid] = pk2(bn_, 0.f);
        }
    }
    __syncthreads();

    int p0 = tile * 512 + tid;           // pixel 0;  pixel 1 = p0 + 256
    int h0 = p0 >> 7, w = p0 & 127;
    int h1 = h0 + 2;

    // load x for both pixels, duplicated into packed lanes
    unsigned long long xv0[16], xv1[16];
    const float* xb = x + ((size_t)(b * 128 + g * 16)) * HWP + p0;
#pragma unroll
    for (int i = 0; i < 16; ++i) {
        float v0 = xb[(size_t)i * HWP];
        float v1 = xb[(size_t)i * HWP + 256];
        xv0[i] = pk2(v0, v0);
        xv1[i] = pk2(v1, v1);
    }

    // interpolation setup (branch uniform per block; w shared by both pixels)
    int br = g >> 1;
    int nH = (br == 0) ? 1 : (br == 1) ? 11 : (br == 2) ? 3 : 5;
    int nW = (br == 0) ? 11 : (br == 1) ? 1 : (br == 2) ? 5 : 3;
    int ci = (br == 1) ? 1 : (br == 2) ? 5 : (br == 3) ? 3 : 0;

    float fw = 0.f; int j0 = 0;
    if (nW > 1) {
        float s = (float)(w * (nW - 1)) * (1.f / 127.f);
        j0 = (int)s; if (j0 > nW - 2) j0 = nW - 2;
        fw = s - (float)j0;
    }
    float fh0 = 0.f; int i00 = 0;
    float fh1 = 0.f; int i01 = 0;
    if (nH > 1) {
        float s0 = (float)(h0 * (nH - 1)) * (1.f / 127.f);
        i00 = (int)s0; if (i00 > nH - 2) i00 = nH - 2;
        fh0 = s0 - (float)i00;
        float s1 = (float)(h1 * (nH - 1)) * (1.f / 127.f);
        i01 = (int)s1; if (i01 > nH - 2) i01 = nH - 2;
        fh1 = s1 - (float)i01;
    }
    int pA = i00 * ci + j0;
    int pB = i01 * ci + j0;
    float a00 = (1.f - fh0) * (1.f - fw), a01 = (1.f - fh0) * fw;
    float a10 = fh0 * (1.f - fw),         a11 = fh0 * fw;
    float c00 = (1.f - fh1) * (1.f - fw), c01 = (1.f - fh1) * fw;
    float c10 = fh1 * (1.f - fw),         c11 = fh1 * fw;
    unsigned long long a00d = pk2(a00, a00), a01d = pk2(a01, a01);
    unsigned long long a10d = pk2(a10, a10), a11d = pk2(a11, a11);
    unsigned long long c00d = pk2(c00, c00), c01d = pk2(c01, c01);
    unsigned long long c10d = pk2(c10, c10), c11d = pk2(c11, c11);

    float* ob = out + ((size_t)(b * 256 + g)) * HWP + p0;

#pragma unroll 2
    for (int o = 0; o < 32; ++o) {
        unsigned long long bA = sbA[o];
        unsigned long long bB = sbB[o];
        unsigned long long accA0 = bA, accB0 = bB;
        unsigned long long accA1 = bA, accB1 = bB;
        const ulonglong2* A2 = (const ulonglong2*)(sWA + o * 16);
        const ulonglong2* B2 = (const ulonglong2*)(sWB + o * 16);
#pragma unroll
        for (int k = 0; k < 8; ++k) {
            ulonglong2 wa = A2[k];
            ulonglong2 wb = B2[k];
            accA0 = fma2(wa.x, xv0[2 * k],     accA0);
            accA0 = fma2(wa.y, xv0[2 * k + 1], accA0);
            accB0 = fma2(wb.x, xv0[2 * k],     accB0);
            accB0 = fma2(wb.y, xv0[2 * k + 1], accB0);
            accA1 = fma2(wa.x, xv1[2 * k],     accA1);
            accA1 = fma2(wa.y, xv1[2 * k + 1], accA1);
            accB1 = fma2(wb.x, xv1[2 * k],     accB1);
            accB1 = fma2(wb.y, xv1[2 * k + 1], accB1);
        }

        const unsigned long long* gpo = sGIp + o * 16;
        const float* gno = sGIn + o * 16;

        // ---- pixel 0 ----
        {
            float hr, hz, hn, cg;
            upk2(hr, hz, accA0);
            upk2(hn, cg, accB0);
            const unsigned long long* gp = gpo + pA;
            unsigned long long irz = mul2(a00d, gp[0]);
            irz = fma2(a01d, gp[1],      irz);
            irz = fma2(a10d, gp[ci],     irz);
            irz = fma2(a11d, gp[ci + 1], irz);
            float ir, iz;
            upk2(ir, iz, irz);
            const float* gn = gno + pA;
            float inn = a00 * gn[0] + a01 * gn[1] + a10 * gn[ci] + a11 * gn[ci + 1];

            float r = sigf(ir + hr);
            float z = sigf(iz + hz);
            float nt = tanhfast(inn + r * hn);
            float y = nt + z * (cg - nt);
            ob[(size_t)(o * 8) * HWP] = y;
        }
        // ---- pixel 1 ----
        {
            float hr, hz, hn, cg;
            upk2(hr, hz, accA1);
            upk2(hn, cg, accB1);
            const unsigned long long* gp = gpo + pB;
            unsigned long long irz = mul2(c00d, gp[0]);
            irz = fma2(c01d, gp[1],      irz);
            irz = fma2(c10d, gp[ci],     irz);
            irz = fma2(c11d, gp[ci + 1], irz);
            float ir, iz;
            upk2(ir, iz, irz);
            const float* gn = gno + pB;
            float inn = c00 * gn[0] + c01 * gn[1] + c10 * gn[ci] + c11 * gn[ci + 1];

            float r = sigf(ir + hr);
            float z = sigf(iz + hz);
            float nt = tanhfast(inn + r * hn);
            float y = nt + z * (cg - nt);
            ob[(size_t)(o * 8) * HWP + 256] = y;
        }
    }
}

// ---------------------------------------------------------------------------
extern "C" void kernel_launch(void* const* d_in, const int* in_sizes, int n_in,
                              void* d_out, int out_size) {
    (void)in_sizes; (void)n_in; (void)out_size;
    const float* x   = (const float*)d_in[0];
    const float* Wc  = (const float*)d_in[1];
    const float* W0  = (const float*)d_in[2];
    const float* b0  = (const float*)d_in[3];
    const float* W1  = (const float*)d_in[4];
    const float* b1  = (const float*)d_in[5];
    const float* W2  = (const float*)d_in[6];
    const float* b2  = (const float*)d_in[7];
    const float* W3  = (const float*)d_in[8];
    const float* b3  = (const float*)d_in[9];
    const float* Wm  = (const float*)d_in[10];
    const float* Wih = (const float*)d_in[11];
    const float* Whh = (const float*)d_in[12];
    const float* bih = (const float*)d_in[13];
    const float* bhh = (const float*)d_in[14];
    float* out = (float*)d_out;

    k_pool<<<BB * CIN, 128>>>(x);
    k_qgi<<<BB * GG + GG, 512>>>(Wm, W0, b0, W1, b1, W2, b2, W3, b3, Wih, bih, Whh, Wc);
    k_main<<<BB * GG * (HWP / 512), 256>>>(x, bhh, out);
}

// round 7
// speedup vs baseline: 2.0620x; 1.0544x over previous
#include <cuda_runtime.h>
#include <cstdint>

// Problem constants
#define BB   8
#define CIN  128
#define HH   128
#define WW   128
#define HWP  (HH*WW)          // 16384
#define COUT 256
#define GG   8

// Scratch (static device globals — no allocation)
__device__ float  d_P[BB * CIN * 52];          // pooled grids: [b][ch][52]
__device__ float2 d_GIp[BB * GG * 32 * 16];    // (gi_r, gi_z) packed grids
__device__ float  d_GIn[BB * GG * 32 * 16];    // gi_n grids
__device__ float2 d_WpackA[GG * 32 * 16];      // (Wcomb_r, Wcomb_z) per group
__device__ float2 d_WpackB[GG * 32 * 16];      // (Wcomb_n, W_center) per group

// ---- packed f32x2 helpers (FFMA2 — only reachable via PTX) ----------------
__device__ __forceinline__ unsigned long long pk2(float lo, float hi) {
    unsigned long long r;
    asm("mov.b64 %0, {%1,%2};" : "=l"(r) : "f"(lo), "f"(hi));
    return r;
}
__device__ __forceinline__ void upk2(float& lo, float& hi, unsigned long long v) {
    asm("mov.b64 {%0,%1}, %2;" : "=f"(lo), "=f"(hi) : "l"(v));
}
__device__ __forceinline__ unsigned long long fma2(unsigned long long a,
                                                   unsigned long long b,
                                                   unsigned long long c) {
    unsigned long long d;
    asm("fma.rn.f32x2 %0, %1, %2, %3;" : "=l"(d) : "l"(a), "l"(b), "l"(c));
    return d;
}
__device__ __forceinline__ unsigned long long mul2(unsigned long long a,
                                                   unsigned long long b) {
    unsigned long long d;
    asm("mul.rn.f32x2 %0, %1, %2;" : "=l"(d) : "l"(a), "l"(b));
    return d;
}
__device__ __forceinline__ unsigned long long add2(unsigned long long a,
                                                   unsigned long long b) {
    unsigned long long d;
    asm("add.rn.f32x2 %0, %1, %2;" : "=l"(d) : "l"(a), "l"(b));
    return d;
}
__device__ __forceinline__ float tanha(float a) {
    float r;
    asm("tanh.approx.f32 %0, %1;" : "=f"(r) : "f"(a));
    return r;
}

// ---------------------------------------------------------------------------
// K1: adaptive average pooling via independent row-segment sums.
// The 20 h-bins for target heights {1,11,3,5} (floor-start/ceil-end bins, may
// overlap by one row) are sums of 33 disjoint row segments with boundaries
// BND[]. Segment sums are independent (no serial cumsum chain). Phase 2 maps
// segments -> 20 per-column h-bin rows in smem. Phase 3 reduces along w.
// ---------------------------------------------------------------------------
__device__ constexpr int BND[34] = {
    0,11,12,23,24,25,26,34,35,42,43,46,47,51,52,58,59,
    69,70,76,77,81,82,85,86,93,94,102,103,104,105,116,117,128};
// h-bin -> segment range [HB_S, HB_E). Bins: [0]=full, [1..11]=O11, [12..14]=O3, [15..19]=O5
__device__ constexpr int HB_S[20] = {0,  0,1,3,7,11,15,17,21,25,29,31,  0,9,23,  0,5,13,19,27};
__device__ constexpr int HB_E[20] = {33, 2,4,8,12,16,18,22,26,30,32,33, 10,24,33, 6,14,20,28,33};

__global__ void k_pool(const float* __restrict__ x) {
    __shared__ float Hs[20 * 128];
    __shared__ float P11[11 * 4];

    int w = threadIdx.x;           // 0..127
    int bc = blockIdx.x;           // b*128+ch
    const float* xp = x + (size_t)bc * HWP + w;

    float seg[33];
#pragma unroll
    for (int s = 0; s < 33; ++s) {
        float c = 0.f;
#pragma unroll
        for (int h = BND[s]; h < BND[s + 1]; ++h) c += xp[h * 128];
        seg[s] = c;
    }

#pragma unroll
    for (int bi = 0; bi < 20; ++bi) {
        float v = 0.f;
#pragma unroll
        for (int s = HB_S[bi]; s < HB_E[bi]; ++s) v += seg[s];
        Hs[bi * 128 + w] = v;
    }
    __syncthreads();

    int t = threadIdx.x;
    // helper threads: partial sums for br1 (each bin sums a full 128-row)
    if (t >= 64 && t < 108) {
        int u = t - 64; int i = u >> 2, q = u & 3;
        const float* Hp = &Hs[(1 + i) * 128 + q * 32];
        float s = 0.f;
#pragma unroll
        for (int k = 0; k < 32; ++k) s += Hp[k];
        P11[i * 4 + q] = s;
    }
    __syncthreads();

    if (t < 52) {
        float sum = 0.f;
        float cnt;
        if (t < 11) {                 // br0 (1,11): full H, w-bins O=11
            int j = t;
            int s = (j * 128) / 11, e = ((j + 1) * 128 + 10) / 11;
            for (int ww = s; ww < e; ++ww) sum += Hs[ww];
            cnt = 128.f * (float)(e - s);
        } else if (t < 22) {          // br1 (11,1)
            int i = t - 11;
            int sH = (i * 128) / 11, eH = ((i + 1) * 128 + 10) / 11;
            sum = (P11[i * 4] + P11[i * 4 + 1]) + (P11[i * 4 + 2] + P11[i * 4 + 3]);
            cnt = (float)(eH - sH) * 128.f;
        } else if (t < 37) {          // br2 (3,5)
            int u = t - 22; int i = u / 5, j = u % 5;
            int sH = (i * 128) / 3, eH = ((i + 1) * 128 + 2) / 3;
            int s = (j * 128) / 5, e = ((j + 1) * 128 + 4) / 5;
            const float* Hp = &Hs[(12 + i) * 128];
            for (int ww = s; ww < e; ++ww) sum += Hp[ww];
            cnt = (float)(eH - sH) * (float)(e - s);
        } else {                      // br3 (5,3)
            int u = t - 37; int i = u / 3, j = u % 3;
            int sH = (i * 128) / 5, eH = ((i + 1) * 128 + 4) / 5;
            int s = (j * 128) / 3, e = ((j + 1) * 128 + 2) / 3;
            const float* Hp = &Hs[(15 + i) * 128];
            for (int ww = s; ww < e; ++ww) sum += Hp[ww];
            cnt = (float)(eH - sH) * (float)(e - s);
        }
        d_P[bc * 52 + t] = sum / cnt;
    }
}

// ---------------------------------------------------------------------------
// K2 (fused k_q + k_gi + k_wcomb):
//   blocks 0..63  : per-channel spatial linear + merge conv -> Q (smem),
//                   then GRU input projection -> packed GI grids.
//   blocks 64..71 : Wcomb = Whh @ W_center, stored as interleaved gate pairs.
// ---------------------------------------------------------------------------
__global__ void k_qgi(const float* __restrict__ Wm,
                      const float* __restrict__ W0, const float* __restrict__ b0,
                      const float* __restrict__ W1, const float* __restrict__ b1,
                      const float* __restrict__ W2, const float* __restrict__ b2,
                      const float* __restrict__ W3, const float* __restrict__ b3,
                      const float* __restrict__ Wih, const float* __restrict__ bih,
                      const float* __restrict__ Whh, const float* __restrict__ Wc) {
    __shared__ float ssh[32 * 16];
    int t = threadIdx.x;               // 512 threads

    if (blockIdx.x >= 64) {
        // ---- wcomb part ----
        int g = blockIdx.x - 64;
        ssh[t] = Wc[g * 512 + t];
        __syncthreads();

        int o = t >> 4, i = t & 15;
        const float* Wr = &Whh[(size_t)(g * 96 + o) * 32];
        const float* Wz = Wr + 32 * 32;
        const float* Wn = Wz + 32 * 32;
        float ar = 0.f, az = 0.f, an = 0.f;
#pragma unroll
        for (int h = 0; h < 32; ++h) {
            float c = ssh[h * 16 + i];
            ar += Wr[h] * c;
            az += Wz[h] * c;
            an += Wn[h] * c;
        }
        d_WpackA[(size_t)g * 512 + t] = make_float2(ar, az);
        d_WpackB[(size_t)g * 512 + t] = make_float2(an, ssh[t]);
        return;
    }

    // ---- qgi part ----
    int bg = blockIdx.x;               // 0..63
    int b = bg >> 3, g = bg & 7;
    int br = g >> 1;
    const float* Wl; const float* bl; int cdim, base;
    if (br == 0)      { Wl = W0; bl = b0; cdim = 11; base = 0;  }
    else if (br == 1) { Wl = W1; bl = b1; cdim = 11; base = 11; }
    else if (br == 2) { Wl = W2; bl = b2; cdim = 15; base = 22; }
    else              { Wl = W3; bl = b3; cdim = 15; base = 37; }

    int ml = t >> 4, u = t & 15;
    float outq = 0.f;
    if (u < cdim) {
        int gl = ml >> 1, o = ml & 1;
        int gm = 16 * g + gl;
#pragma unroll
        for (int j = 0; j < 4; ++j) {
            int ch = 64 * (g & 1) + 4 * gl + j;
            const float* Pp = &d_P[(b * 128 + ch) * 52 + base];
            float q = bl[u];
            for (int v = 0; v < cdim; ++v) q += Wl[u * cdim + v] * Pp[v];
            outq += Wm[gm * 8 + o * 4 + j] * q;
        }
    }
    ssh[t] = outq;
    __syncthreads();

    int o = t >> 4;                    // 0..31
    float ar = bih[g * 96 + o];
    float az = bih[g * 96 + 32 + o];
    float an = bih[g * 96 + 64 + o];
    const float* Wr = &Wih[(size_t)(g * 96 + o) * 32];
    const float* Wz = Wr + 32 * 32;
    const float* Wn = Wz + 32 * 32;
#pragma unroll
    for (int ml2 = 0; ml2 < 32; ++ml2) {
        float q = ssh[ml2 * 16 + u];
        ar += Wr[ml2] * q;
        az += Wz[ml2] * q;
        an += Wn[ml2] * q;
    }
    d_GIp[(size_t)bg * 512 + t] = make_float2(ar, az);
    d_GIn[(size_t)bg * 512 + t] = an;
}

// ---------------------------------------------------------------------------
// K3: main fused kernel — packed f32x2 gates, 2 pixels per thread.
// r/z sigmoids via tanh.approx (1 MUFU each); n-gate tanh exact path.
// ---------------------------------------------------------------------------
__device__ __forceinline__ float tanhfast(float a) {
    float e = __expf(-2.f * a);
    return __fdividef(2.f, 1.f + e) - 1.f;
}

__global__ void __launch_bounds__(256, 2) k_main(const float* __restrict__ x,
                                                 const float* __restrict__ bhh,
                                                 float* __restrict__ out) {
    __shared__ __align__(16) unsigned long long sWA[512];
    __shared__ __align__(16) unsigned long long sWB[512];
    __shared__ __align__(16) unsigned long long sGIp[512];
    __shared__ float sGIn[512];
    __shared__ unsigned long long sbA[32];
    __shared__ unsigned long long sbB[32];

    int tid = threadIdx.x;
    int tile = blockIdx.x & 31;          // 32 tiles of 512 pixels
    int g    = (blockIdx.x >> 5) & 7;
    int b    = blockIdx.x >> 8;

    {
        const unsigned long long* wa = (const unsigned long long*)(d_WpackA + (size_t)g * 512);
        const unsigned long long* wb = (const unsigned long long*)(d_WpackB + (size_t)g * 512);
        const unsigned long long* gp = (const unsigned long long*)(d_GIp + (size_t)(b * 8 + g) * 512);
        const float* gn = d_GIn + (size_t)(b * 8 + g) * 512;
        for (int i = tid; i < 512; i += 256) {
            sWA[i]  = wa[i];
            sWB[i]  = wb[i];
            sGIp[i] = gp[i];
            sGIn[i] = gn[i];
        }
        if (tid < 32) {
            float br_ = bhh[g * 96 + tid];
            float bz_ = bhh[g * 96 + 32 + tid];
            float bn_ = bhh[g * 96 + 64 + tid];
            sbA[tid] = pk2(br_, bz_);
            sbB[tid] = pk2(bn_, 0.f);
        }
    }
    __syncthreads();

    int p0 = tile * 512 + tid;           // pixel 0;  pixel 1 = p0 + 256
    int h0 = p0 >> 7, w = p0 & 127;
    int h1 = h0 + 2;

    // load x for both pixels, duplicated into packed lanes
    unsigned long long xv0[16], xv1[16];
    const float* xb = x + ((size_t)(b * 128 + g * 16)) * HWP + p0;
#pragma unroll
    for (int i = 0; i < 16; ++i) {
        float v0 = xb[(size_t)i * HWP];
        float v1 = xb[(size_t)i * HWP + 256];
        xv0[i] = pk2(v0, v0);
        xv1[i] = pk2(v1, v1);
    }

    // interpolation setup (branch uniform per block; w shared by both pixels)
    int br = g >> 1;
    int nH = (br == 0) ? 1 : (br == 1) ? 11 : (br == 2) ? 3 : 5;
    int nW = (br == 0) ? 11 : (br == 1) ? 1 : (br == 2) ? 5 : 3;
    int ci = (br == 1) ? 1 : (br == 2) ? 5 : (br == 3) ? 3 : 0;

    float fw = 0.f; int j0 = 0;
    if (nW > 1) {
        float s = (float)(w * (nW - 1)) * (1.f / 127.f);
        j0 = (int)s; if (j0 > nW - 2) j0 = nW - 2;
        fw = s - (float)j0;
    }
    float fh0 = 0.f; int i00 = 0;
    float fh1 = 0.f; int i01 = 0;
    if (nH > 1) {
        float s0 = (float)(h0 * (nH - 1)) * (1.f / 127.f);
        i00 = (int)s0; if (i00 > nH - 2) i00 = nH - 2;
        fh0 = s0 - (float)i00;
        float s1 = (float)(h1 * (nH - 1)) * (1.f / 127.f);
        i01 = (int)s1; if (i01 > nH - 2) i01 = nH - 2;
        fh1 = s1 - (float)i01;
    }
    int pA = i00 * ci + j0;
    int pB = i01 * ci + j0;
    float a00 = (1.f - fh0) * (1.f - fw), a01 = (1.f - fh0) * fw;
    float a10 = fh0 * (1.f - fw),         a11 = fh0 * fw;
    float c00 = (1.f - fh1) * (1.f - fw), c01 = (1.f - fh1) * fw;
    float c10 = fh1 * (1.f - fw),         c11 = fh1 * fw;
    unsigned long long a00d = pk2(a00, a00), a01d = pk2(a01, a01);
    unsigned long long a10d = pk2(a10, a10), a11d = pk2(a11, a11);
    unsigned long long c00d = pk2(c00, c00), c01d = pk2(c01, c01);
    unsigned long long c10d = pk2(c10, c10), c11d = pk2(c11, c11);

    float* ob = out + ((size_t)(b * 256 + g)) * HWP + p0;

#pragma unroll 2
    for (int o = 0; o < 32; ++o) {
        unsigned long long bA = sbA[o];
        unsigned long long bB = sbB[o];
        unsigned long long accA0 = bA, accB0 = bB;
        unsigned long long accA1 = bA, accB1 = bB;
        const ulonglong2* A2 = (const ulonglong2*)(sWA + o * 16);
        const ulonglong2* B2 = (const ulonglong2*)(sWB + o * 16);
#pragma unroll
        for (int k = 0; k < 8; ++k) {
            ulonglong2 wa = A2[k];
            ulonglong2 wb = B2[k];
            accA0 = fma2(wa.x, xv0[2 * k],     accA0);
            accA0 = fma2(wa.y, xv0[2 * k + 1], accA0);
            accB0 = fma2(wb.x, xv0[2 * k],     accB0);
            accB0 = fma2(wb.y, xv0[2 * k + 1], accB0);
            accA1 = fma2(wa.x, xv1[2 * k],     accA1);
            accA1 = fma2(wa.y, xv1[2 * k + 1], accA1);
            accB1 = fma2(wb.x, xv1[2 * k],     accB1);
            accB1 = fma2(wb.y, xv1[2 * k + 1], accB1);
        }

        const unsigned long long* gpo = sGIp + o * 16;
        const float* gno = sGIn + o * 16;

        // ---- pixel 0 ----
        {
            const unsigned long long* gp = gpo + pA;
            unsigned long long irz = mul2(a00d, gp[0]);
            irz = fma2(a01d, gp[1],      irz);
            irz = fma2(a10d, gp[ci],     irz);
            irz = fma2(a11d, gp[ci + 1], irz);
            unsigned long long srz = add2(irz, accA0);   // (ir+hr, iz+hz)
            float vr, vz;
            upk2(vr, vz, srz);
            float hn, cg;
            upk2(hn, cg, accB0);
            const float* gn = gno + pA;
            float inn = a00 * gn[0] + a01 * gn[1] + a10 * gn[ci] + a11 * gn[ci + 1];

            float r = fmaf(0.5f, tanha(0.5f * vr), 0.5f);
            float z = fmaf(0.5f, tanha(0.5f * vz), 0.5f);
            float nt = tanhfast(inn + r * hn);
            float y = nt + z * (cg - nt);
            ob[(size_t)(o * 8) * HWP] = y;
        }
        // ---- pixel 1 ----
        {
            const unsigned long long* gp = gpo + pB;
            unsigned long long irz = mul2(c00d, gp[0]);
            irz = fma2(c01d, gp[1],      irz);
            irz = fma2(c10d, gp[ci],     irz);
            irz = fma2(c11d, gp[ci + 1], irz);
            unsigned long long srz = add2(irz, accA1);
            float vr, vz;
            upk2(vr, vz, srz);
            float hn, cg;
            upk2(hn, cg, accB1);
            const float* gn = gno + pB;
            float inn = c00 * gn[0] + c01 * gn[1] + c10 * gn[ci] + c11 * gn[ci + 1];

            float r = fmaf(0.5f, tanha(0.5f * vr), 0.5f);
            float z = fmaf(0.5f, tanha(0.5f * vz), 0.5f);
            float nt = tanhfast(inn + r * hn);
            float y = nt + z * (cg - nt);
            ob[(size_t)(o * 8) * HWP + 256] = y;
        }
    }
}

// ---------------------------------------------------------------------------
extern "C" void kernel_launch(void* const* d_in, const int* in_sizes, int n_in,
                              void* d_out, int out_size) {
    (void)in_sizes; (void)n_in; (void)out_size;
    const float* x   = (const float*)d_in[0];
    const float* Wc  = (const float*)d_in[1];
    const float* W0  = (const float*)d_in[2];
    const float* b0  = (const float*)d_in[3];
    const float* W1  = (const float*)d_in[4];
    const float* b1  = (const float*)d_in[5];
    const float* W2  = (const float*)d_in[6];
    const float* b2  = (const float*)d_in[7];
    const float* W3  = (const float*)d_in[8];
    const float* b3  = (const float*)d_in[9];
    const float* Wm  = (const float*)d_in[10];
    const float* Wih = (const float*)d_in[11];
    const float* Whh = (const float*)d_in[12];
    const float* bih = (const float*)d_in[13];
    const float* bhh = (const float*)d_in[14];
    float* out = (float*)d_out;

    k_pool<<<BB * CIN, 128>>>(x);
    k_qgi<<<BB * GG + GG, 512>>>(Wm, W0, b0, W1, b1, W2, b2, W3, b3, Wih, bih, Whh, Wc);
    k_main<<<BB * GG * (HWP / 512), 256>>>(x, bhh, out);
}